// round 2
// baseline (speedup 1.0000x reference)
#include <cuda_runtime.h>
#include <cstdint>

// Problem constants
#define BB 4
#define HH 12
#define TT 2048
#define DD 64
#define CC 768

// Scratch (device globals: allocation-free per harness rules)
__device__ float g_Q[BB * HH * TT * DD];
__device__ float g_K[BB * HH * TT * DD];
__device__ float g_V[BB * HH * TT * DD];
__device__ float g_O[BB * TT * CC];

// ---------------------------------------------------------------------------
// tf32 helpers (legacy tensor-core path; tcgen05 port planned next round)
// ---------------------------------------------------------------------------
__device__ __forceinline__ unsigned f2tf(float x) {
    unsigned r;
    asm("cvt.rna.tf32.f32 %0, %1;" : "=r"(r) : "f"(x));
    return r;
}

__device__ __forceinline__ void mma8(float* c, const unsigned* a, const unsigned* b) {
    asm volatile(
        "mma.sync.aligned.m16n8k8.row.col.f32.tf32.tf32.f32 "
        "{%0,%1,%2,%3},{%4,%5,%6,%7},{%8,%9},{%0,%1,%2,%3};"
        : "+f"(c[0]), "+f"(c[1]), "+f"(c[2]), "+f"(c[3])
        : "r"(a[0]), "r"(a[1]), "r"(a[2]), "r"(a[3]), "r"(b[0]), "r"(b[1]));
}

// ---------------------------------------------------------------------------
// 3xTF32 GEMM:  out[M,N] = A[M,768] @ W[768,N] + bias
// MODE 0: A = x, N=2304, scatter into g_Q/g_K/g_V as [B,H,T,64]
// MODE 1: A = g_O (ignores A arg), N=768, write [M,N] to out
// CTA tile 128x128, Ktile 32, 8 warps (4m x 2n), warp tile 32x64.
// ---------------------------------------------------------------------------
template <int MODE>
__global__ void __launch_bounds__(256) gemm3x(const float* __restrict__ A,
                                              const float* __restrict__ W,
                                              const float* __restrict__ bias,
                                              float* __restrict__ out, int N) {
    __shared__ float As[128][33];
    __shared__ float Bs[32][132];

    const int tid = threadIdx.x;
    const int w = tid >> 5, lane = tid & 31;
    const int g = lane >> 2, cq = lane & 3;
    const int m0 = blockIdx.y * 128, n0 = blockIdx.x * 128;
    const int mo = (w >> 1) * 32, no = (w & 1) * 64;

    const float* Ap = (MODE == 1) ? (const float*)g_O : A;

    float acc[2][8][4];
#pragma unroll
    for (int i = 0; i < 2; i++)
#pragma unroll
        for (int j = 0; j < 8; j++)
#pragma unroll
            for (int k = 0; k < 4; k++) acc[i][j][k] = 0.f;

    for (int kt = 0; kt < 24; kt++) {
        __syncthreads();
        // A tile 128x32 (row stride 768, both x and g_O have 768 cols)
        const float* Ag = Ap + (size_t)m0 * 768 + kt * 32;
#pragma unroll
        for (int i = 0; i < 4; i++) {
            int f = tid + i * 256;
            int r = f >> 3, c4 = f & 7;
            float4 v = *reinterpret_cast<const float4*>(Ag + (size_t)r * 768 + c4 * 4);
            As[r][c4 * 4 + 0] = v.x; As[r][c4 * 4 + 1] = v.y;
            As[r][c4 * 4 + 2] = v.z; As[r][c4 * 4 + 3] = v.w;
        }
        // B tile 32x128
        const float* Wg = W + (size_t)(kt * 32) * N + n0;
#pragma unroll
        for (int i = 0; i < 4; i++) {
            int f = tid + i * 256;
            int r = f >> 5, c4 = f & 31;
            float4 v = *reinterpret_cast<const float4*>(Wg + (size_t)r * N + c4 * 4);
            Bs[r][c4 * 4 + 0] = v.x; Bs[r][c4 * 4 + 1] = v.y;
            Bs[r][c4 * 4 + 2] = v.z; Bs[r][c4 * 4 + 3] = v.w;
        }
        __syncthreads();

#pragma unroll
        for (int kk = 0; kk < 4; kk++) {
            unsigned aH[2][4], aL[2][4];
#pragma unroll
            for (int mt = 0; mt < 2; mt++) {
#pragma unroll
                for (int i = 0; i < 4; i++) {
                    int r = mo + mt * 16 + g + (i & 1) * 8;
                    int cidx = kk * 8 + cq + (i >> 1) * 4;
                    float v = As[r][cidx];
                    unsigned hi = f2tf(v);
                    aH[mt][i] = hi;
                    aL[mt][i] = f2tf(v - __uint_as_float(hi));
                }
            }
            unsigned bH[8][2], bL[8][2];
#pragma unroll
            for (int nt = 0; nt < 8; nt++) {
#pragma unroll
                for (int i = 0; i < 2; i++) {
                    int kidx = kk * 8 + cq + i * 4;
                    int nidx = no + nt * 8 + g;
                    float v = Bs[kidx][nidx];
                    unsigned hi = f2tf(v);
                    bH[nt][i] = hi;
                    bL[nt][i] = f2tf(v - __uint_as_float(hi));
                }
            }
#pragma unroll
            for (int mt = 0; mt < 2; mt++)
#pragma unroll
                for (int nt = 0; nt < 8; nt++) {
                    mma8(acc[mt][nt], aH[mt], bH[nt]);
                    mma8(acc[mt][nt], aL[mt], bH[nt]);
                    mma8(acc[mt][nt], aH[mt], bL[nt]);
                }
        }
    }

    // Epilogue
#pragma unroll
    for (int mt = 0; mt < 2; mt++) {
#pragma unroll
        for (int nt = 0; nt < 8; nt++) {
#pragma unroll
            for (int half = 0; half < 2; half++) {
                int gm = m0 + mo + mt * 16 + g + half * 8;
                int gn = n0 + no + nt * 8 + 2 * cq;
                float v0 = acc[mt][nt][half * 2 + 0] + bias[gn];
                float v1 = acc[mt][nt][half * 2 + 1] + bias[gn + 1];
                if (MODE == 0) {
                    int sel = gn / 768;
                    int wn = gn - sel * 768;
                    int h = wn >> 6, d = wn & 63;
                    int b = gm >> 11, t = gm & 2047;
                    float* p = (sel == 0) ? g_Q : ((sel == 1) ? g_K : g_V);
                    size_t idx = (((size_t)b * HH + h) * TT + t) * DD + d;
                    *reinterpret_cast<float2*>(p + idx) = make_float2(v0, v1);
                } else {
                    *reinterpret_cast<float2*>(out + (size_t)gm * 768 + gn) =
                        make_float2(v0, v1);
                }
            }
        }
    }
}

// ---------------------------------------------------------------------------
// Flash attention: CTA = (q-tile of 128, b*h). 8 warps, each owns a 16-row
// strip. K/V tiles of 64 streamed; FIRE mask added (causality comes from the
// mask's -1e9 entries; strictly-above-diagonal tiles are skipped exactly).
// tf32 mma for QK^T and PV, fp32 softmax state.
// ---------------------------------------------------------------------------
#define FLASH_SMEM_FLOATS (128 * 65 + 64 * 65 + 64 * 65)

__global__ void __launch_bounds__(256) flash_kernel(const float* __restrict__ mask) {
    extern __shared__ float sm[];
    float* Qs = sm;                 // [128][65]; reused as P after Q frag extraction
    float* Ks = sm + 128 * 65;      // [64][65]
    float* Vs = Ks + 64 * 65;       // [64][65]

    const int tid = threadIdx.x;
    const int w = tid >> 5, lane = tid & 31;
    const int g = lane >> 2, cq = lane & 3;
    const int q0 = blockIdx.x * 128;
    const int bh = blockIdx.y;
    const int b = bh / HH, h = bh - b * HH;

    const float* Qg = g_Q + (size_t)bh * TT * DD;
    const float* Kg = g_K + (size_t)bh * TT * DD;
    const float* Vg = g_V + (size_t)bh * TT * DD;

    // Load Q tile [128][64]
#pragma unroll
    for (int i = 0; i < 8; i++) {
        int f = tid + i * 256;
        int r = f >> 4, c4 = f & 15;
        float4 v = *reinterpret_cast<const float4*>(Qg + (size_t)(q0 + r) * 64 + c4 * 4);
        float* d = Qs + r * 65 + c4 * 4;
        d[0] = v.x; d[1] = v.y; d[2] = v.z; d[3] = v.w;
    }
    __syncthreads();

    // Extract Q fragments (tf32), rows of this warp's 16-row strip
    unsigned qf[8][4];
    {
        int r0 = w * 16;
#pragma unroll
        for (int kk = 0; kk < 8; kk++) {
            qf[kk][0] = f2tf(Qs[(r0 + g) * 65 + kk * 8 + cq]);
            qf[kk][1] = f2tf(Qs[(r0 + g + 8) * 65 + kk * 8 + cq]);
            qf[kk][2] = f2tf(Qs[(r0 + g) * 65 + kk * 8 + cq + 4]);
            qf[kk][3] = f2tf(Qs[(r0 + g + 8) * 65 + kk * 8 + cq + 4]);
        }
    }

    float mI[2] = {-1e30f, -1e30f};
    float lI[2] = {0.f, 0.f};
    float o[8][4];
#pragma unroll
    for (int nt = 0; nt < 8; nt++)
#pragma unroll
        for (int i = 0; i < 4; i++) o[nt][i] = 0.f;

    const float* mbase = mask + ((size_t)h * TT + (q0 + w * 16 + g)) * TT;

    const int jend = q0 + 128;  // causal skip: tiles with j0 >= q0+128 contribute 0 exactly
    for (int j0 = 0; j0 < jend; j0 += 64) {
        __syncthreads();
        // Load K,V tiles [64][64] (store tf32-rounded)
#pragma unroll
        for (int i = 0; i < 4; i++) {
            int f = tid + i * 256;
            int r = f >> 4, c4 = f & 15;
            float4 kv = *reinterpret_cast<const float4*>(Kg + (size_t)(j0 + r) * 64 + c4 * 4);
            float4 vv = *reinterpret_cast<const float4*>(Vg + (size_t)(j0 + r) * 64 + c4 * 4);
            float* kd = Ks + r * 65 + c4 * 4;
            kd[0] = __uint_as_float(f2tf(kv.x)); kd[1] = __uint_as_float(f2tf(kv.y));
            kd[2] = __uint_as_float(f2tf(kv.z)); kd[3] = __uint_as_float(f2tf(kv.w));
            float* vd = Vs + r * 65 + c4 * 4;
            vd[0] = __uint_as_float(f2tf(vv.x)); vd[1] = __uint_as_float(f2tf(vv.y));
            vd[2] = __uint_as_float(f2tf(vv.z)); vd[3] = __uint_as_float(f2tf(vv.w));
        }
        __syncthreads();

        // S = Q K^T  (warp strip: 16 x 64)
        float s[8][4];
#pragma unroll
        for (int nt = 0; nt < 8; nt++)
#pragma unroll
            for (int i = 0; i < 4; i++) s[nt][i] = 0.f;
#pragma unroll
        for (int kk = 0; kk < 8; kk++) {
#pragma unroll
            for (int nt = 0; nt < 8; nt++) {
                unsigned bf[2] = {
                    __float_as_uint(Ks[(nt * 8 + g) * 65 + kk * 8 + cq]),
                    __float_as_uint(Ks[(nt * 8 + g) * 65 + kk * 8 + cq + 4])};
                mma8(s[nt], qf[kk], bf);
            }
        }

        // scale + FIRE mask, row max
        float rmax0 = -1e30f, rmax1 = -1e30f;
#pragma unroll
        for (int nt = 0; nt < 8; nt++) {
            int col = j0 + nt * 8 + 2 * cq;
            float2 mk0 = *reinterpret_cast<const float2*>(mbase + col);
            float2 mk1 = *reinterpret_cast<const float2*>(mbase + (size_t)8 * TT + col);
            s[nt][0] = s[nt][0] * 0.125f + mk0.x;
            s[nt][1] = s[nt][1] * 0.125f + mk0.y;
            s[nt][2] = s[nt][2] * 0.125f + mk1.x;
            s[nt][3] = s[nt][3] * 0.125f + mk1.y;
            rmax0 = fmaxf(rmax0, fmaxf(s[nt][0], s[nt][1]));
            rmax1 = fmaxf(rmax1, fmaxf(s[nt][2], s[nt][3]));
        }
        rmax0 = fmaxf(rmax0, __shfl_xor_sync(0xffffffffu, rmax0, 1));
        rmax0 = fmaxf(rmax0, __shfl_xor_sync(0xffffffffu, rmax0, 2));
        rmax1 = fmaxf(rmax1, __shfl_xor_sync(0xffffffffu, rmax1, 1));
        rmax1 = fmaxf(rmax1, __shfl_xor_sync(0xffffffffu, rmax1, 2));

        float mn0 = fmaxf(mI[0], rmax0), mn1 = fmaxf(mI[1], rmax1);
        float al0 = __expf(mI[0] - mn0), al1 = __expf(mI[1] - mn1);

        float rs0 = 0.f, rs1 = 0.f;
#pragma unroll
        for (int nt = 0; nt < 8; nt++) {
            s[nt][0] = __expf(s[nt][0] - mn0); rs0 += s[nt][0];
            s[nt][1] = __expf(s[nt][1] - mn0); rs0 += s[nt][1];
            s[nt][2] = __expf(s[nt][2] - mn1); rs1 += s[nt][2];
            s[nt][3] = __expf(s[nt][3] - mn1); rs1 += s[nt][3];
        }
        rs0 += __shfl_xor_sync(0xffffffffu, rs0, 1);
        rs0 += __shfl_xor_sync(0xffffffffu, rs0, 2);
        rs1 += __shfl_xor_sync(0xffffffffu, rs1, 1);
        rs1 += __shfl_xor_sync(0xffffffffu, rs1, 2);

        lI[0] = lI[0] * al0 + rs0;
        lI[1] = lI[1] * al1 + rs1;
        mI[0] = mn0;
        mI[1] = mn1;

#pragma unroll
        for (int nt = 0; nt < 8; nt++) {
            o[nt][0] *= al0; o[nt][1] *= al0;
            o[nt][2] *= al1; o[nt][3] *= al1;
        }

        // Stage P (tf32) into warp-private smem strip (aliases Qs rows)
        float* Pw = Qs + (w * 16) * 65;
#pragma unroll
        for (int nt = 0; nt < 8; nt++) {
            int col = nt * 8 + 2 * cq;
            Pw[g * 65 + col] = __uint_as_float(f2tf(s[nt][0]));
            Pw[g * 65 + col + 1] = __uint_as_float(f2tf(s[nt][1]));
            Pw[(g + 8) * 65 + col] = __uint_as_float(f2tf(s[nt][2]));
            Pw[(g + 8) * 65 + col + 1] = __uint_as_float(f2tf(s[nt][3]));
        }
        __syncwarp();

        // O += P @ V
#pragma unroll
        for (int kk = 0; kk < 8; kk++) {
            unsigned a[4] = {
                __float_as_uint(Pw[g * 65 + kk * 8 + cq]),
                __float_as_uint(Pw[(g + 8) * 65 + kk * 8 + cq]),
                __float_as_uint(Pw[g * 65 + kk * 8 + cq + 4]),
                __float_as_uint(Pw[(g + 8) * 65 + kk * 8 + cq + 4])};
#pragma unroll
            for (int nt = 0; nt < 8; nt++) {
                unsigned bfv[2] = {
                    __float_as_uint(Vs[(kk * 8 + cq) * 65 + nt * 8 + g]),
                    __float_as_uint(Vs[(kk * 8 + cq + 4) * 65 + nt * 8 + g])};
                mma8(o[nt], a, bfv);
            }
        }
        __syncwarp();
    }

    // Normalize and write O as [B,T,C] for the projection GEMM
    float inv0 = 1.f / lI[0], inv1 = 1.f / lI[1];
    float* Og = g_O + ((size_t)b * TT) * CC + (size_t)h * 64;
#pragma unroll
    for (int nt = 0; nt < 8; nt++) {
        int row0 = q0 + w * 16 + g;
        int dcol = nt * 8 + 2 * cq;
        *reinterpret_cast<float2*>(Og + (size_t)row0 * CC + dcol) =
            make_float2(o[nt][0] * inv0, o[nt][1] * inv0);
        *reinterpret_cast<float2*>(Og + (size_t)(row0 + 8) * CC + dcol) =
            make_float2(o[nt][2] * inv1, o[nt][3] * inv1);
    }
}

// ---------------------------------------------------------------------------
extern "C" void kernel_launch(void* const* d_in, const int* in_sizes, int n_in,
                              void* d_out, int out_size) {
    const float* x    = (const float*)d_in[0];
    const float* mask = (const float*)d_in[1];
    const float* Wqkv = (const float*)d_in[2];
    const float* bqkv = (const float*)d_in[3];
    const float* Wp   = (const float*)d_in[4];
    const float* bp   = (const float*)d_in[5];
    float* out = (float*)d_out;

    const int smem_bytes = FLASH_SMEM_FLOATS * (int)sizeof(float);  // 66560
    cudaFuncSetAttribute(flash_kernel, cudaFuncAttributeMaxDynamicSharedMemorySize,
                         smem_bytes);

    // 1) QKV = x @ W_attn + b_attn, scattered to [B,H,T,64]
    dim3 g0(2304 / 128, (BB * TT) / 128);  // (18, 64)
    gemm3x<0><<<g0, 256>>>(x, Wqkv, bqkv, nullptr, 2304);

    // 2) Fused causal flash attention with FIRE mask
    dim3 gf(TT / 128, BB * HH);  // (16, 48)
    flash_kernel<<<gf, 256, smem_bytes>>>(mask);

    // 3) out = O @ W_proj + b_proj
    dim3 g1(768 / 128, (BB * TT) / 128);  // (6, 64)
    gemm3x<1><<<g1, 256>>>(nullptr, Wp, bp, out, 768);
}

// round 3
// speedup vs baseline: 1.5342x; 1.5342x over previous
#include <cuda_runtime.h>
#include <cuda_bf16.h>
#include <cstdint>

// Problem constants
#define BB 4
#define HH 12
#define TT 2048
#define DD 64
#define CC 768

// Scratch (device globals: allocation-free per harness rules)
__device__ float g_Q[BB * HH * TT * DD];
__device__ float g_K[BB * HH * TT * DD];
__device__ float g_V[BB * HH * TT * DD];
__device__ float g_O[BB * TT * CC];

// ---------------------------------------------------------------------------
// helpers
// ---------------------------------------------------------------------------
__device__ __forceinline__ unsigned f2tf(float x) {
    unsigned r;
    asm("cvt.rna.tf32.f32 %0, %1;" : "=r"(r) : "f"(x));
    return r;
}

// tf32 m16n8k8 (attention)
__device__ __forceinline__ void mma8(float* c, const unsigned* a, const unsigned* b) {
    asm volatile(
        "mma.sync.aligned.m16n8k8.row.col.f32.tf32.tf32.f32 "
        "{%0,%1,%2,%3},{%4,%5,%6,%7},{%8,%9},{%0,%1,%2,%3};"
        : "+f"(c[0]), "+f"(c[1]), "+f"(c[2]), "+f"(c[3])
        : "r"(a[0]), "r"(a[1]), "r"(a[2]), "r"(a[3]), "r"(b[0]), "r"(b[1]));
}

// bf16 m16n8k16 (GEMMs)
__device__ __forceinline__ void mma16(float* c, const unsigned* a, const unsigned* b) {
    asm volatile(
        "mma.sync.aligned.m16n8k16.row.col.f32.bf16.bf16.f32 "
        "{%0,%1,%2,%3},{%4,%5,%6,%7},{%8,%9},{%0,%1,%2,%3};"
        : "+f"(c[0]), "+f"(c[1]), "+f"(c[2]), "+f"(c[3])
        : "r"(a[0]), "r"(a[1]), "r"(a[2]), "r"(a[3]), "r"(b[0]), "r"(b[1]));
}

__device__ __forceinline__ unsigned pack_hi(float a, float b) {
    __nv_bfloat162 h = __floats2bfloat162_rn(a, b);
    return *reinterpret_cast<unsigned*>(&h);
}
__device__ __forceinline__ void split2(float a, float b, unsigned& hi, unsigned& lo) {
    __nv_bfloat162 h = __floats2bfloat162_rn(a, b);
    float la = a - __bfloat162float(h.x);
    float lb = b - __bfloat162float(h.y);
    __nv_bfloat162 l = __floats2bfloat162_rn(la, lb);
    hi = *reinterpret_cast<unsigned*>(&h);
    lo = *reinterpret_cast<unsigned*>(&l);
}

// ---------------------------------------------------------------------------
// bf16x3 GEMM:  out[M,N] = A[M,768] @ W[768,N] + bias   (fp32-class accuracy)
// MODE 0: A = x, N=2304, scatter into g_Q/g_K/g_V as [B,H,T,64]
// MODE 1: A = g_O, N=768, write [M,N] to out
// CTA tile 128x128, Ktile 32, 8 warps (4m x 2n), warp tile 32x64.
// hi/lo bf16 split done ONCE at smem-store time; k-pairs packed into uint32
// matching the m16n8k16 fragment layout (conflict-free padded strides).
// ---------------------------------------------------------------------------
template <int MODE>
__global__ void __launch_bounds__(256, 2) gemm_bf16x3(const float* __restrict__ A,
                                                      const float* __restrict__ W,
                                                      const float* __restrict__ bias,
                                                      float* __restrict__ out, int N) {
    __shared__ unsigned Ahi[128][20];   // [row][kp] kp=k/2 packed pairs, pad 16->20
    __shared__ unsigned Alo[128][20];
    __shared__ unsigned Bhi[16][136];   // [kp][n] pad 128->136
    __shared__ unsigned Blo[16][136];

    const int tid = threadIdx.x;
    const int w = tid >> 5, lane = tid & 31;
    const int g = lane >> 2, cq = lane & 3;
    const int m0 = blockIdx.y * 128, n0 = blockIdx.x * 128;
    const int mo = (w >> 1) * 32, no = (w & 1) * 64;

    const float* Ap = (MODE == 1) ? (const float*)g_O : A;

    float acc[2][8][4];
#pragma unroll
    for (int i = 0; i < 2; i++)
#pragma unroll
        for (int j = 0; j < 8; j++)
#pragma unroll
            for (int k = 0; k < 4; k++) acc[i][j][k] = 0.f;

    for (int kt = 0; kt < 24; kt++) {
        __syncthreads();
        // --- A tile 128x32, convert+split at store time ---
        const float* Ag = Ap + (size_t)m0 * 768 + kt * 32;
#pragma unroll
        for (int i = 0; i < 4; i++) {
            int f = tid + i * 256;
            int r = f >> 3, c4 = f & 7;
            float4 v = *reinterpret_cast<const float4*>(Ag + (size_t)r * 768 + c4 * 4);
            unsigned h0, l0, h1, l1;
            split2(v.x, v.y, h0, l0);
            split2(v.z, v.w, h1, l1);
            Ahi[r][c4 * 2] = h0; Ahi[r][c4 * 2 + 1] = h1;
            Alo[r][c4 * 2] = l0; Alo[r][c4 * 2 + 1] = l1;
        }
        // --- B tile 32x128, transpose k-pairs into packed uint32 ---
#pragma unroll
        for (int i = 0; i < 2; i++) {
            int f = tid + i * 256;
            int kp = f >> 5, n4 = f & 31;
            const float* Wg = W + (size_t)(kt * 32 + 2 * kp) * N + n0 + n4 * 4;
            float4 v = *reinterpret_cast<const float4*>(Wg);
            float4 u = *reinterpret_cast<const float4*>(Wg + N);
            unsigned h[4], l[4];
            split2(v.x, u.x, h[0], l[0]);
            split2(v.y, u.y, h[1], l[1]);
            split2(v.z, u.z, h[2], l[2]);
            split2(v.w, u.w, h[3], l[3]);
            *reinterpret_cast<uint4*>(&Bhi[kp][n4 * 4]) = make_uint4(h[0], h[1], h[2], h[3]);
            *reinterpret_cast<uint4*>(&Blo[kp][n4 * 4]) = make_uint4(l[0], l[1], l[2], l[3]);
        }
        __syncthreads();

#pragma unroll
        for (int kk = 0; kk < 2; kk++) {
            unsigned ah[2][4], al[2][4];
#pragma unroll
            for (int mt = 0; mt < 2; mt++) {
                int r0 = mo + mt * 16;
                int kp0 = kk * 8 + cq;
                ah[mt][0] = Ahi[r0 + g][kp0];
                ah[mt][1] = Ahi[r0 + g + 8][kp0];
                ah[mt][2] = Ahi[r0 + g][kp0 + 4];
                ah[mt][3] = Ahi[r0 + g + 8][kp0 + 4];
                al[mt][0] = Alo[r0 + g][kp0];
                al[mt][1] = Alo[r0 + g + 8][kp0];
                al[mt][2] = Alo[r0 + g][kp0 + 4];
                al[mt][3] = Alo[r0 + g + 8][kp0 + 4];
            }
#pragma unroll
            for (int nt = 0; nt < 8; nt++) {
                int col = no + nt * 8 + g;
                int kp0 = kk * 8 + cq;
                unsigned bh[2] = {Bhi[kp0][col], Bhi[kp0 + 4][col]};
                unsigned bl[2] = {Blo[kp0][col], Blo[kp0 + 4][col]};
#pragma unroll
                for (int mt = 0; mt < 2; mt++) {
                    mma16(acc[mt][nt], ah[mt], bh);
                    mma16(acc[mt][nt], al[mt], bh);
                    mma16(acc[mt][nt], ah[mt], bl);
                }
            }
        }
    }

    // Epilogue
#pragma unroll
    for (int mt = 0; mt < 2; mt++) {
#pragma unroll
        for (int nt = 0; nt < 8; nt++) {
#pragma unroll
            for (int half = 0; half < 2; half++) {
                int gm = m0 + mo + mt * 16 + g + half * 8;
                int gn = n0 + no + nt * 8 + 2 * cq;
                float v0 = acc[mt][nt][half * 2 + 0] + bias[gn];
                float v1 = acc[mt][nt][half * 2 + 1] + bias[gn + 1];
                if (MODE == 0) {
                    int sel = gn / 768;
                    int wn = gn - sel * 768;
                    int h = wn >> 6, d = wn & 63;
                    int b = gm >> 11, t = gm & 2047;
                    float* p = (sel == 0) ? g_Q : ((sel == 1) ? g_K : g_V);
                    size_t idx = (((size_t)b * HH + h) * TT + t) * DD + d;
                    *reinterpret_cast<float2*>(p + idx) = make_float2(v0, v1);
                } else {
                    *reinterpret_cast<float2*>(out + (size_t)gm * 768 + gn) =
                        make_float2(v0, v1);
                }
            }
        }
    }
}

// ---------------------------------------------------------------------------
// Flash attention: CTA = (q-tile of 64, b*h), 128 threads (4 warps, 16 rows
// each). 3 CTAs/SM resident (regs capped via launch_bounds) for latency
// hiding. K/V tiles of 64 streamed; FIRE mask prefetched to registers before
// the QK MMA loop. tf32 mma for QK^T and PV, fp32 softmax state.
// ---------------------------------------------------------------------------
#define QROWS 64
#define FLASH_SMEM_FLOATS (QROWS * 65 + 64 * 65 + 64 * 65)

__global__ void __launch_bounds__(128, 3) flash_kernel(const float* __restrict__ mask) {
    extern __shared__ float sm[];
    float* Qs = sm;                   // [64][65]; reused as P staging
    float* Ks = sm + QROWS * 65;      // [64][65]
    float* Vs = Ks + 64 * 65;         // [64][65]

    const int tid = threadIdx.x;
    const int w = tid >> 5, lane = tid & 31;
    const int g = lane >> 2, cq = lane & 3;
    const int q0 = blockIdx.x * QROWS;
    const int bh = blockIdx.y;
    const int b = bh / HH, h = bh - b * HH;

    const float* Qg = g_Q + (size_t)bh * TT * DD;
    const float* Kg = g_K + (size_t)bh * TT * DD;
    const float* Vg = g_V + (size_t)bh * TT * DD;

    // Load Q tile [64][64]
#pragma unroll
    for (int i = 0; i < 8; i++) {
        int f = tid + i * 128;
        int r = f >> 4, c4 = f & 15;
        float4 v = *reinterpret_cast<const float4*>(Qg + (size_t)(q0 + r) * 64 + c4 * 4);
        float* d = Qs + r * 65 + c4 * 4;
        d[0] = v.x; d[1] = v.y; d[2] = v.z; d[3] = v.w;
    }
    __syncthreads();

    // Extract Q fragments (tf32), rows of this warp's 16-row strip
    unsigned qf[8][4];
    {
        int r0 = w * 16;
#pragma unroll
        for (int kk = 0; kk < 8; kk++) {
            qf[kk][0] = f2tf(Qs[(r0 + g) * 65 + kk * 8 + cq]);
            qf[kk][1] = f2tf(Qs[(r0 + g + 8) * 65 + kk * 8 + cq]);
            qf[kk][2] = f2tf(Qs[(r0 + g) * 65 + kk * 8 + cq + 4]);
            qf[kk][3] = f2tf(Qs[(r0 + g + 8) * 65 + kk * 8 + cq + 4]);
        }
    }

    float mI[2] = {-1e30f, -1e30f};
    float lI[2] = {0.f, 0.f};
    float o[8][4];
#pragma unroll
    for (int nt = 0; nt < 8; nt++)
#pragma unroll
        for (int i = 0; i < 4; i++) o[nt][i] = 0.f;

    const float* mbase = mask + ((size_t)h * TT + (q0 + w * 16 + g)) * TT;

    const int jend = q0 + QROWS;  // causal skip: tiles beyond this contribute 0 exactly
    for (int j0 = 0; j0 < jend; j0 += 64) {
        __syncthreads();
        // Load K,V tiles [64][64] (store tf32-rounded)
#pragma unroll
        for (int i = 0; i < 8; i++) {
            int f = tid + i * 128;
            int r = f >> 4, c4 = f & 15;
            float4 kv = *reinterpret_cast<const float4*>(Kg + (size_t)(j0 + r) * 64 + c4 * 4);
            float4 vv = *reinterpret_cast<const float4*>(Vg + (size_t)(j0 + r) * 64 + c4 * 4);
            float* kd = Ks + r * 65 + c4 * 4;
            kd[0] = __uint_as_float(f2tf(kv.x)); kd[1] = __uint_as_float(f2tf(kv.y));
            kd[2] = __uint_as_float(f2tf(kv.z)); kd[3] = __uint_as_float(f2tf(kv.w));
            float* vd = Vs + r * 65 + c4 * 4;
            vd[0] = __uint_as_float(f2tf(vv.x)); vd[1] = __uint_as_float(f2tf(vv.y));
            vd[2] = __uint_as_float(f2tf(vv.z)); vd[3] = __uint_as_float(f2tf(vv.w));
        }
        __syncthreads();

        // Prefetch FIRE mask for this tile (LDG latency hides behind MMAs below)
        float2 mk0[8], mk1[8];
#pragma unroll
        for (int nt = 0; nt < 8; nt++) {
            int col = j0 + nt * 8 + 2 * cq;
            mk0[nt] = *reinterpret_cast<const float2*>(mbase + col);
            mk1[nt] = *reinterpret_cast<const float2*>(mbase + (size_t)8 * TT + col);
        }

        // S = Q K^T  (warp strip: 16 x 64)
        float s[8][4];
#pragma unroll
        for (int nt = 0; nt < 8; nt++)
#pragma unroll
            for (int i = 0; i < 4; i++) s[nt][i] = 0.f;
#pragma unroll
        for (int kk = 0; kk < 8; kk++) {
#pragma unroll
            for (int nt = 0; nt < 8; nt++) {
                unsigned bf[2] = {
                    __float_as_uint(Ks[(nt * 8 + g) * 65 + kk * 8 + cq]),
                    __float_as_uint(Ks[(nt * 8 + g) * 65 + kk * 8 + cq + 4])};
                mma8(s[nt], qf[kk], bf);
            }
        }

        // scale + FIRE mask, row max
        float rmax0 = -1e30f, rmax1 = -1e30f;
#pragma unroll
        for (int nt = 0; nt < 8; nt++) {
            s[nt][0] = s[nt][0] * 0.125f + mk0[nt].x;
            s[nt][1] = s[nt][1] * 0.125f + mk0[nt].y;
            s[nt][2] = s[nt][2] * 0.125f + mk1[nt].x;
            s[nt][3] = s[nt][3] * 0.125f + mk1[nt].y;
            rmax0 = fmaxf(rmax0, fmaxf(s[nt][0], s[nt][1]));
            rmax1 = fmaxf(rmax1, fmaxf(s[nt][2], s[nt][3]));
        }
        rmax0 = fmaxf(rmax0, __shfl_xor_sync(0xffffffffu, rmax0, 1));
        rmax0 = fmaxf(rmax0, __shfl_xor_sync(0xffffffffu, rmax0, 2));
        rmax1 = fmaxf(rmax1, __shfl_xor_sync(0xffffffffu, rmax1, 1));
        rmax1 = fmaxf(rmax1, __shfl_xor_sync(0xffffffffu, rmax1, 2));

        float mn0 = fmaxf(mI[0], rmax0), mn1 = fmaxf(mI[1], rmax1);
        float al0 = __expf(mI[0] - mn0), al1 = __expf(mI[1] - mn1);

        float rs0 = 0.f, rs1 = 0.f;
#pragma unroll
        for (int nt = 0; nt < 8; nt++) {
            s[nt][0] = __expf(s[nt][0] - mn0); rs0 += s[nt][0];
            s[nt][1] = __expf(s[nt][1] - mn0); rs0 += s[nt][1];
            s[nt][2] = __expf(s[nt][2] - mn1); rs1 += s[nt][2];
            s[nt][3] = __expf(s[nt][3] - mn1); rs1 += s[nt][3];
        }
        rs0 += __shfl_xor_sync(0xffffffffu, rs0, 1);
        rs0 += __shfl_xor_sync(0xffffffffu, rs0, 2);
        rs1 += __shfl_xor_sync(0xffffffffu, rs1, 1);
        rs1 += __shfl_xor_sync(0xffffffffu, rs1, 2);

        lI[0] = lI[0] * al0 + rs0;
        lI[1] = lI[1] * al1 + rs1;
        mI[0] = mn0;
        mI[1] = mn1;

#pragma unroll
        for (int nt = 0; nt < 8; nt++) {
            o[nt][0] *= al0; o[nt][1] *= al0;
            o[nt][2] *= al1; o[nt][3] *= al1;
        }

        // Stage P (tf32) into warp-private smem strip (aliases Qs rows)
        float* Pw = Qs + (w * 16) * 65;
#pragma unroll
        for (int nt = 0; nt < 8; nt++) {
            int col = nt * 8 + 2 * cq;
            Pw[g * 65 + col] = __uint_as_float(f2tf(s[nt][0]));
            Pw[g * 65 + col + 1] = __uint_as_float(f2tf(s[nt][1]));
            Pw[(g + 8) * 65 + col] = __uint_as_float(f2tf(s[nt][2]));
            Pw[(g + 8) * 65 + col + 1] = __uint_as_float(f2tf(s[nt][3]));
        }
        __syncwarp();

        // O += P @ V
#pragma unroll
        for (int kk = 0; kk < 8; kk++) {
            unsigned a[4] = {
                __float_as_uint(Pw[g * 65 + kk * 8 + cq]),
                __float_as_uint(Pw[(g + 8) * 65 + kk * 8 + cq]),
                __float_as_uint(Pw[g * 65 + kk * 8 + cq + 4]),
                __float_as_uint(Pw[(g + 8) * 65 + kk * 8 + cq + 4])};
#pragma unroll
            for (int nt = 0; nt < 8; nt++) {
                unsigned bfv[2] = {
                    __float_as_uint(Vs[(kk * 8 + cq) * 65 + nt * 8 + g]),
                    __float_as_uint(Vs[(kk * 8 + cq + 4) * 65 + nt * 8 + g])};
                mma8(o[nt], a, bfv);
            }
        }
        __syncwarp();
    }

    // Normalize and write O as [B,T,C] for the projection GEMM
    float inv0 = 1.f / lI[0], inv1 = 1.f / lI[1];
    float* Og = g_O + ((size_t)b * TT) * CC + (size_t)h * 64;
#pragma unroll
    for (int nt = 0; nt < 8; nt++) {
        int row0 = q0 + w * 16 + g;
        int dcol = nt * 8 + 2 * cq;
        *reinterpret_cast<float2*>(Og + (size_t)row0 * CC + dcol) =
            make_float2(o[nt][0] * inv0, o[nt][1] * inv0);
        *reinterpret_cast<float2*>(Og + (size_t)(row0 + 8) * CC + dcol) =
            make_float2(o[nt][2] * inv1, o[nt][3] * inv1);
    }
}

// ---------------------------------------------------------------------------
extern "C" void kernel_launch(void* const* d_in, const int* in_sizes, int n_in,
                              void* d_out, int out_size) {
    const float* x    = (const float*)d_in[0];
    const float* mask = (const float*)d_in[1];
    const float* Wqkv = (const float*)d_in[2];
    const float* bqkv = (const float*)d_in[3];
    const float* Wp   = (const float*)d_in[4];
    const float* bp   = (const float*)d_in[5];
    float* out = (float*)d_out;

    const int smem_bytes = FLASH_SMEM_FLOATS * (int)sizeof(float);  // 49920
    cudaFuncSetAttribute(flash_kernel, cudaFuncAttributeMaxDynamicSharedMemorySize,
                         smem_bytes);

    // 1) QKV = x @ W_attn + b_attn, scattered to [B,H,T,64]
    dim3 g0(2304 / 128, (BB * TT) / 128);  // (18, 64)
    gemm_bf16x3<0><<<g0, 256>>>(x, Wqkv, bqkv, nullptr, 2304);

    // 2) Fused causal flash attention with FIRE mask
    dim3 gf(TT / QROWS, BB * HH);  // (32, 48)
    flash_kernel<<<gf, 128, smem_bytes>>>(mask);

    // 3) out = O @ W_proj + b_proj
    dim3 g1(768 / 128, (BB * TT) / 128);  // (6, 64)
    gemm_bf16x3<1><<<g1, 256>>>(nullptr, Wp, bp, out, 768);
}